// round 1
// baseline (speedup 1.0000x reference)
#include <cuda_runtime.h>
#include <math.h>
#include <float.h>

#define NN    512
#define FIN   256
#define HF    64
#define NC    64
#define TOPK  12
#define LALPHA 0.2f
#define MAXE  32
#define MAXR  16   // max distinct rows/cols (math guarantees <= 11)

// ---------------- scratch (device globals; no allocation allowed) ----------
__device__ float g_A[NN * NN];
__device__ float g_cand[128 * TOPK];
__device__ float g_kth;
__device__ int   g_ne_raw;
__device__ int   g_ei_raw[MAXE], g_ej_raw[MAXE];
__device__ int   g_ne, g_nrows, g_ncols;
__device__ int   g_ei[MAXE], g_ej[MAXE], g_erow[MAXE], g_ecol[MAXE];
__device__ int   g_rows[MAXR], g_cols[MAXR];
__device__ float g_w1[NN * FIN];
__device__ float g_w2[NN * FIN];
__device__ float g_WhN[(size_t)NN * MAXR * HF];   // [h][colidx][k]
__device__ float g_E2T[NN * NN];                  // [h][j]
__device__ float g_mid[(size_t)MAXR * NN * HF];   // [rowidx][h*64+k]
__device__ float g_part[128 * MAXR * NC];
__device__ float g_WhOut[MAXR * NC];

__device__ __forceinline__ float lrelu(float x) { return x >= 0.f ? x : LALPHA * x; }
__device__ __forceinline__ float elu1(float x)  { return x > 0.f ? x : expm1f(x); }

// ---------------- k_init: zero feat region + counters ----------------------
__global__ void k_init(float* outp) {
    int idx = blockIdx.x * 256 + threadIdx.x;
    if (outp && idx < NN * NC) outp[idx] = 0.f;
    if (idx == 0) g_ne_raw = 0;
}

// ---------------- k_vvt: A = V V^T -----------------------------------------
__global__ void k_vvt(const float* __restrict__ V) {
    __shared__ float sI[16][65], sJ[16][65];
    int i0 = blockIdx.y * 16, j0 = blockIdx.x * 16;
    int t = threadIdx.y * 16 + threadIdx.x;
    for (int e = t; e < 16 * 64; e += 256) {
        int r = e >> 6, c = e & 63;
        sI[r][c] = V[(i0 + r) * HF + c];
        sJ[r][c] = V[(j0 + r) * HF + c];
    }
    __syncthreads();
    float s = 0.f;
#pragma unroll
    for (int k = 0; k < 64; k++) s += sI[threadIdx.y][k] * sJ[threadIdx.x][k];
    g_A[(i0 + threadIdx.y) * NN + j0 + threadIdx.x] = s;
}

// ---------------- top-12 (with multiplicity): 2 phases ----------------------
// Phase A: 128 blocks, each finds top-12 of its 2048 values (iterative max
// with single-instance removal -> multiplicity preserved).
__global__ void k_topA() {
    __shared__ float buf[2048];
    __shared__ float sPart[16];
    __shared__ float sMax;
    __shared__ int   sClaim;
    int t = threadIdx.x;                     // 512
    int base = blockIdx.x * 2048;
    for (int e = t; e < 2048; e += 512) buf[e] = g_A[base + e];
    __syncthreads();
    for (int it = 0; it < TOPK; it++) {
        float m = -FLT_MAX;
        for (int e = t; e < 2048; e += 512) m = fmaxf(m, buf[e]);
        for (int o = 16; o; o >>= 1) m = fmaxf(m, __shfl_xor_sync(~0u, m, o));
        if ((t & 31) == 0) sPart[t >> 5] = m;
        if (t == 0) sClaim = 0;
        __syncthreads();
        if (t == 0) {
            float mm = sPart[0];
            for (int w = 1; w < 16; w++) mm = fmaxf(mm, sPart[w]);
            sMax = mm;
            g_cand[blockIdx.x * TOPK + it] = mm;
        }
        __syncthreads();
        float mm = sMax;
        for (int e = t; e < 2048; e += 512) {
            if (buf[e] == mm) {
                if (atomicAdd(&sClaim, 1) == 0) buf[e] = -FLT_MAX;
            }
        }
        __syncthreads();
    }
}

// Phase B: 1 block over 1536 candidates; 12th max -> g_kth
__global__ void k_topB() {
    __shared__ float buf[1536];
    __shared__ float sPart[16];
    __shared__ float sMax;
    __shared__ int   sClaim;
    int t = threadIdx.x;                     // 512
    for (int e = t; e < 1536; e += 512) buf[e] = g_cand[e];
    __syncthreads();
    for (int it = 0; it < TOPK; it++) {
        float m = -FLT_MAX;
        for (int e = t; e < 1536; e += 512) m = fmaxf(m, buf[e]);
        for (int o = 16; o; o >>= 1) m = fmaxf(m, __shfl_xor_sync(~0u, m, o));
        if ((t & 31) == 0) sPart[t >> 5] = m;
        if (t == 0) sClaim = 0;
        __syncthreads();
        if (t == 0) {
            float mm = sPart[0];
            for (int w = 1; w < 16; w++) mm = fmaxf(mm, sPart[w]);
            sMax = mm;
            if (it == TOPK - 1) g_kth = mm;
        }
        __syncthreads();
        float mm = sMax;
        for (int e = t; e < 1536; e += 512) {
            if (buf[e] == mm) {
                if (atomicAdd(&sClaim, 1) == 0) buf[e] = -FLT_MAX;
            }
        }
        __syncthreads();
    }
}

// ---------------- k_adj: write adj output + compact edges -------------------
__global__ void k_adj(float* adj_out) {
    int idx = blockIdx.x * 256 + threadIdx.x;
    if (idx >= NN * NN) return;
    float v = g_A[idx];
    float o = (v > g_kth) ? 1.f : 0.f;
    if (adj_out) adj_out[idx] = o;
    if (o != 0.f) {
        int s = atomicAdd(&g_ne_raw, 1);
        if (s < MAXE) { g_ei_raw[s] = idx >> 9; g_ej_raw[s] = idx & 511; }
    }
}

// ---------------- k_prep: sort edges, build row/col index maps --------------
__global__ void k_prep() {
    int ne = g_ne_raw; if (ne > MAXE) ne = MAXE;
    int ei[MAXE], ej[MAXE];
    for (int e = 0; e < ne; e++) { ei[e] = g_ei_raw[e]; ej[e] = g_ej_raw[e]; }
    for (int a = 1; a < ne; a++) {                       // insertion sort by (i,j)
        int ki = ei[a], kj = ej[a]; int key = ki * NN + kj; int b = a - 1;
        while (b >= 0 && ei[b] * NN + ej[b] > key) { ei[b+1] = ei[b]; ej[b+1] = ej[b]; b--; }
        ei[b+1] = ki; ej[b+1] = kj;
    }
    int nr = 0, ncl = 0;
    int rows[MAXR], cols[MAXR];
    int e;
    for (e = 0; e < ne; e++) {
        int r = -1; for (int q = 0; q < nr; q++) if (rows[q] == ei[e]) r = q;
        int c = -1; for (int q = 0; q < ncl; q++) if (cols[q] == ej[e]) c = q;
        if (r < 0 && nr >= MAXR) break;
        if (c < 0 && ncl >= MAXR) break;
        if (r < 0) { r = nr; rows[nr++] = ei[e]; }
        if (c < 0) { c = ncl; cols[ncl++] = ej[e]; }
        g_ei[e] = ei[e]; g_ej[e] = ej[e]; g_erow[e] = r; g_ecol[e] = c;
    }
    g_ne = e; g_nrows = nr; g_ncols = ncl;
    for (int q = 0; q < nr; q++)  g_rows[q] = rows[q];
    for (int q = 0; q < ncl; q++) g_cols[q] = cols[q];
}

// ---------------- k_head: stream W_stack once per head ----------------------
// Outputs per head h: w1[256], w2[256], WhN[ncols][64]
__global__ void __launch_bounds__(256) k_head(const float* __restrict__ X,
                                              const float* __restrict__ Wst,
                                              const float* __restrict__ ast) {
    __shared__ float sW[64 * 68];
    __shared__ float sXc[MAXR * 256];
    __shared__ float sA[128];
    int h = blockIdx.x, t = threadIdx.x;
    int ncols = g_ncols; if (ncols > MAXR) ncols = MAXR;
    if (t < 128) sA[t] = ast[h * 128 + t];
    for (int e = t; e < MAXR * 256; e += 256) {
        int c = e >> 8, f = e & 255;
        sXc[e] = (c < ncols) ? X[g_cols[c] * FIN + f] : 0.f;
    }
    float acc[4] = {0.f, 0.f, 0.f, 0.f};
    int kk = t & 63, jg = t >> 6;
    const float* Wh = Wst + (size_t)h * FIN * HF;
    for (int ft = 0; ft < 4; ft++) {
        __syncthreads();
        const float4* src = (const float4*)(Wh + ft * 64 * 64);
        for (int q = t; q < 1024; q += 256) {
            float4 v = src[q];
            int flat = q * 4; int fl = flat >> 6; int k = flat & 63;
            *(float4*)&sW[fl * 68 + k] = v;
        }
        __syncthreads();
        {   // w1/w2: thread group of 4 per f
            int fl = t >> 2, qq = t & 3, k0 = qq * 16;
            float s1 = 0.f, s2 = 0.f;
#pragma unroll
            for (int k = 0; k < 16; k++) {
                float w = sW[fl * 68 + k0 + k];
                s1 += w * sA[k0 + k];
                s2 += w * sA[64 + k0 + k];
            }
            s1 += __shfl_xor_sync(~0u, s1, 1); s2 += __shfl_xor_sync(~0u, s2, 1);
            s1 += __shfl_xor_sync(~0u, s1, 2); s2 += __shfl_xor_sync(~0u, s2, 2);
            if (qq == 0) {
                g_w1[h * FIN + ft * 64 + fl] = s1;
                g_w2[h * FIN + ft * 64 + fl] = s2;
            }
        }
        // WhN accumulation: thread = (k, j-group)
#pragma unroll 4
        for (int fl = 0; fl < 64; fl++) {
            float w = sW[fl * 68 + kk];
            int f = ft * 64 + fl;
#pragma unroll
            for (int l = 0; l < 4; l++) acc[l] += sXc[(jg + 4 * l) * 256 + f] * w;
        }
    }
#pragma unroll
    for (int l = 0; l < 4; l++) {
        int jj = jg + 4 * l;
        if (jj < ncols) g_WhN[((size_t)h * MAXR + jj) * HF + kk] = acc[l];
    }
}

// ---------------- k_e2: E2T[h][j] = sum_f w2[h][f] * X[j][f] ----------------
__global__ void __launch_bounds__(256) k_e2(const float* __restrict__ X) {
    __shared__ float sA2[32 * 33], sB2[32 * 33];
    int h0 = blockIdx.y * 32, j0 = blockIdx.x * 32;
    int t = threadIdx.x;
    int ty = t >> 4, tx = t & 15;
    float c00 = 0, c01 = 0, c10 = 0, c11 = 0;
    for (int f0 = 0; f0 < FIN; f0 += 32) {
        __syncthreads();
        for (int e = t; e < 1024; e += 256) {
            int r = e >> 5, f = e & 31;
            sA2[r * 33 + f] = g_w2[(h0 + r) * FIN + f0 + f];
            sB2[r * 33 + f] = X[(j0 + r) * FIN + f0 + f];
        }
        __syncthreads();
#pragma unroll
        for (int f = 0; f < 32; f++) {
            float a0 = sA2[(2 * ty) * 33 + f],     a1 = sA2[(2 * ty + 1) * 33 + f];
            float b0 = sB2[(2 * tx) * 33 + f],     b1 = sB2[(2 * tx + 1) * 33 + f];
            c00 += a0 * b0; c01 += a0 * b1; c10 += a1 * b0; c11 += a1 * b1;
        }
    }
    g_E2T[(h0 + 2 * ty) * NN + j0 + 2 * tx]         = c00;
    g_E2T[(h0 + 2 * ty) * NN + j0 + 2 * tx + 1]     = c01;
    g_E2T[(h0 + 2 * ty + 1) * NN + j0 + 2 * tx]     = c10;
    g_E2T[(h0 + 2 * ty + 1) * NN + j0 + 2 * tx + 1] = c11;
}

// ---------------- k_epi: per-head softmax rows + mid -----------------------
__global__ void __launch_bounds__(256) k_epi(const float* __restrict__ X) {
    __shared__ float sE2[512];
    __shared__ float sE1a[MAXR], sM[MAXR], sDi[MAXR];
    __shared__ float sOut[MAXR * 64];
    __shared__ float sRed[8];
    __shared__ float sMax;
    int h = blockIdx.x, t = threadIdx.x;
    int nrows = g_nrows; if (nrows > MAXR) nrows = MAXR;
    int ne = g_ne;
    sE2[t]       = g_E2T[h * NN + t];
    sE2[t + 256] = g_E2T[h * NN + t + 256];
    __syncthreads();
    // e2max
    float m = fmaxf(sE2[t], sE2[t + 256]);
    for (int o = 16; o; o >>= 1) m = fmaxf(m, __shfl_xor_sync(~0u, m, o));
    if ((t & 31) == 0) sRed[t >> 5] = m;
    __syncthreads();
    if (t == 0) {
        float mm = sRed[0];
        for (int w = 1; w < 8; w++) mm = fmaxf(mm, sRed[w]);
        sMax = mm;
    }
    // E1 at active rows: warp per row
    int wid = t >> 5, lane = t & 31;
    for (int r = wid; r < nrows; r += 8) {
        int i = g_rows[r];
        float s = 0.f;
        for (int f = lane; f < FIN; f += 32) s += X[i * FIN + f] * g_w1[h * FIN + f];
        for (int o = 16; o; o >>= 1) s += __shfl_xor_sync(~0u, s, o);
        if (lane == 0) sE1a[r] = s;
    }
    for (int e = t; e < MAXR * 64; e += 256) sOut[e] = 0.f;
    __syncthreads();
    float e2max = sMax;
    // per-row softmax denominator over full 512 columns (softmax BEFORE mask)
    for (int r = 0; r < nrows; r++) {
        float e1 = sE1a[r];
        float mr = lrelu(e1 + e2max);
        float p = __expf(lrelu(e1 + sE2[t]) - mr) + __expf(lrelu(e1 + sE2[t + 256]) - mr);
        for (int o = 16; o; o >>= 1) p += __shfl_xor_sync(~0u, p, o);
        if ((t & 31) == 0) sRed[t >> 5] = p;
        __syncthreads();
        if (t == 0) {
            float s = 0.f;
            for (int w = 0; w < 8; w++) s += sRed[w];
            sM[r] = mr; sDi[r] = 1.f / s;
        }
        __syncthreads();
    }
    // sparse A @ Wh over edges
    if (t < 64) {
        for (int e = 0; e < ne; e++) {
            int r = g_erow[e], ci = g_ecol[e], j = g_ej[e];
            float alpha = __expf(lrelu(sE1a[r] + sE2[j]) - sM[r]) * sDi[r];
            sOut[r * 64 + t] += alpha * g_WhN[((size_t)h * MAXR + ci) * HF + t];
        }
    }
    __syncthreads();
    for (int e = t; e < nrows * 64; e += 256) {
        int r = e >> 6, k = e & 63;
        g_mid[(size_t)r * (NN * HF) + h * 64 + k] = elu1(sOut[r * 64 + k]);
    }
}

// ---------------- k_midg: split-K GEMM mid_act @ W_out ----------------------
__global__ void __launch_bounds__(256) k_midg(const float* __restrict__ Wout) {
    __shared__ float sMid[MAXR * 256];
    int b = blockIdx.x, t = threadIdx.x;
    int nrows = g_nrows; if (nrows > MAXR) nrows = MAXR;
    int r0 = b * 256;
    for (int e = t; e < MAXR * 256; e += 256) {
        int i = e >> 8, rr = e & 255;
        sMid[e] = (i < nrows) ? g_mid[(size_t)i * (NN * HF) + r0 + rr] : 0.f;
    }
    __syncthreads();
    int c = t & 63, ig = t >> 6;
    float acc[4] = {0.f, 0.f, 0.f, 0.f};
    for (int rr = 0; rr < 256; rr++) {
        float w = Wout[(size_t)(r0 + rr) * NC + c];
#pragma unroll
        for (int l = 0; l < 4; l++) acc[l] += sMid[(ig + 4 * l) * 256 + rr] * w;
    }
#pragma unroll
    for (int l = 0; l < 4; l++)
        g_part[((size_t)b * MAXR + ig + 4 * l) * NC + c] = acc[l];
}

__global__ void k_midred() {
    int t = blockIdx.x * 256 + threadIdx.x;
    if (t < MAXR * NC) {
        float s = 0.f;
        for (int b = 0; b < 128; b++) s += g_part[b * (MAXR * NC) + t];
        g_WhOut[t] = s;
    }
}

// ---------------- k_final: output GAT layer + elu(V*out) --------------------
__global__ void k_final(const float* __restrict__ V, const float* __restrict__ aout,
                        float* __restrict__ outp) {
    __shared__ float sAo[128];
    __shared__ float e1o[MAXR], e2o[MAXR], sM2[MAXR], sD2[MAXR];
    int t = threadIdx.x;
    int nrows = g_nrows; if (nrows > MAXR) nrows = MAXR;
    int ne = g_ne;
    if (nrows == 0 || outp == 0) return;
    if (t < 128) sAo[t] = aout[t];
    __syncthreads();
    int wid = t >> 5, lane = t & 31;
    for (int r = wid; r < nrows; r += 8) {
        float s1 = 0.f, s2 = 0.f;
        for (int f = lane; f < NC; f += 32) {
            float w = g_WhOut[r * NC + f];
            s1 += w * sAo[f]; s2 += w * sAo[64 + f];
        }
        for (int o = 16; o; o >>= 1) {
            s1 += __shfl_xor_sync(~0u, s1, o);
            s2 += __shfl_xor_sync(~0u, s2, o);
        }
        if (lane == 0) { e1o[r] = s1; e2o[r] = s2; }
    }
    __syncthreads();
    if (t == 0) {
        // inactive rows have Wh_out == 0 exactly -> e2o == 0 there; since
        // nrows < 512 those zeros exist, so include 0 in the max.
        float e2m = 0.f;
        for (int r = 0; r < nrows; r++) e2m = fmaxf(e2m, e2o[r]);
        for (int r = 0; r < nrows; r++) {
            float mm = lrelu(e1o[r] + e2m);
            float D = (float)(NN - nrows) * __expf(lrelu(e1o[r]) - mm);
            for (int q = 0; q < nrows; q++) D += __expf(lrelu(e1o[r] + e2o[q]) - mm);
            sM2[r] = mm; sD2[r] = 1.f / D;
        }
    }
    __syncthreads();
    for (int e = t; e < nrows * 64; e += 256) {
        int r = e >> 6, k = e & 63;
        float o2 = 0.f;
        for (int ed = 0; ed < ne; ed++) {
            if (g_erow[ed] != r) continue;
            int j = g_ej[ed];
            int jr = -1;
            for (int q = 0; q < nrows; q++) if (g_rows[q] == j) jr = q;
            if (jr < 0) continue;   // Wh_out[j] == 0 -> contributes nothing
            float alpha = __expf(lrelu(e1o[r] + e2o[jr]) - sM2[r]) * sD2[r];
            o2 += alpha * g_WhOut[jr * NC + k];
        }
        float g = elu1(o2);
        int i = g_rows[r];
        outp[i * NC + k] = elu1(V[i * NC + k] * g);
    }
}

// ---------------- host ------------------------------------------------------
extern "C" void kernel_launch(void* const* d_in, const int* in_sizes, int n_in,
                              void* d_out, int out_size) {
    const float* X    = (const float*)d_in[0];
    const float* Wst  = (const float*)d_in[1];
    const float* ast  = (const float*)d_in[2];
    const float* Wout = (const float*)d_in[3];
    const float* aout = (const float*)d_in[4];
    const float* V    = (const float*)d_in[5];
    float* outbuf = (float*)d_out;

    float* adj_dst  = nullptr;
    float* feat_dst = nullptr;
    if (out_size >= NN * NN + NN * NC) { adj_dst = outbuf; feat_dst = outbuf + NN * NN; }
    else if (out_size == NN * NN)      { adj_dst = outbuf; }
    else                               { feat_dst = outbuf; }

    k_init  <<<128, 256>>>(feat_dst);
    k_vvt   <<<dim3(32, 32), dim3(16, 16)>>>(V);
    k_topA  <<<128, 512>>>();
    k_topB  <<<1, 512>>>();
    k_adj   <<<1024, 256>>>(adj_dst);
    k_prep  <<<1, 1>>>();
    k_head  <<<512, 256>>>(X, Wst, ast);
    k_e2    <<<dim3(16, 16), 256>>>(X);
    k_epi   <<<512, 256>>>(X);
    k_midg  <<<128, 256>>>(Wout);
    k_midred<<<4, 256>>>();
    k_final <<<1, 256>>>(V, aout, feat_dst);
}

// round 3
// speedup vs baseline: 1.1429x; 1.1429x over previous
#include <cuda_runtime.h>
#include <math.h>
#include <float.h>

#define NN    512
#define FIN   256
#define HF    64
#define NC    64
#define TOPK  12
#define LALPHA 0.2f
#define MAXE  32
#define MAXR  16   // max distinct rows/cols (math guarantees <= 11)
#define CAND_CAP 8192

// ---------------- scratch (device globals; no allocation allowed) ----------
__device__ float    g_A[NN * NN];
__device__ unsigned g_hist[2048];
__device__ unsigned g_selbin, g_selrank;
__device__ unsigned g_kthkey;
__device__ int      g_nc2;
__device__ unsigned g_cand2[CAND_CAP];
__device__ int      g_ne_raw;
__device__ int      g_ei_raw[MAXE], g_ej_raw[MAXE];
__device__ int      g_ne, g_nrows, g_ncols;
__device__ int      g_ei[MAXE], g_ej[MAXE], g_erow[MAXE], g_ecol[MAXE];
__device__ int      g_rows[MAXR], g_cols[MAXR];
__device__ float    g_w1[NN * FIN];
__device__ float    g_w2[NN * FIN];
__device__ float    g_WhN[(size_t)NN * MAXR * HF];   // [h][j][k]
__device__ float    g_E2T[NN * NN];                  // [h][j]
__device__ float    g_mid[(size_t)MAXR * NN * HF];   // [rowidx][h*64+k]
__device__ float    g_part[128 * MAXR * NC];
__device__ float    g_WhOut[MAXR * NC];

__device__ __forceinline__ float lrelu(float x) { return x >= 0.f ? x : LALPHA * x; }
__device__ __forceinline__ float elu1(float x)  { return x > 0.f ? x : expm1f(x); }
__device__ __forceinline__ unsigned fkey(float f) {
    unsigned u = __float_as_uint(f);
    return (u & 0x80000000u) ? ~u : (u | 0x80000000u);
}

// ---------------- k_zero: zero feat region + hist + counters ----------------
__global__ void k_zero(float* outp) {
    int idx = blockIdx.x * 256 + threadIdx.x;           // 32768 threads
    if (outp && idx < NN * NC) outp[idx] = 0.f;
    if (idx < 2048) g_hist[idx] = 0u;
    if (idx == 0) { g_ne_raw = 0; g_nc2 = 0; }
}

// ---------------- k_vvt: A = V V^T, fused 2048-bin histogram ---------------
__global__ void __launch_bounds__(256) k_vvt(const float* __restrict__ V) {
    __shared__ float sI[32][33], sJ[32][33];
    __shared__ unsigned sHist[2048];
    int i0 = blockIdx.y * 32, j0 = blockIdx.x * 32;
    int t = threadIdx.x;
    int ty = t >> 4, tx = t & 15;
    for (int e = t; e < 2048; e += 256) sHist[e] = 0u;
    float c00 = 0, c01 = 0, c10 = 0, c11 = 0;
    for (int k0 = 0; k0 < HF; k0 += 32) {
        __syncthreads();
        for (int e = t; e < 1024; e += 256) {
            int r = e >> 5, c = e & 31;
            sI[r][c] = V[(i0 + r) * HF + k0 + c];
            sJ[r][c] = V[(j0 + r) * HF + k0 + c];
        }
        __syncthreads();
#pragma unroll
        for (int k = 0; k < 32; k++) {
            float a0 = sI[2 * ty][k],     a1 = sI[2 * ty + 1][k];
            float b0 = sJ[2 * tx][k],     b1 = sJ[2 * tx + 1][k];
            c00 += a0 * b0; c01 += a0 * b1; c10 += a1 * b0; c11 += a1 * b1;
        }
    }
    int r0 = i0 + 2 * ty, cc0 = j0 + 2 * tx;
    g_A[(r0)     * NN + cc0]     = c00;
    g_A[(r0)     * NN + cc0 + 1] = c01;
    g_A[(r0 + 1) * NN + cc0]     = c10;
    g_A[(r0 + 1) * NN + cc0 + 1] = c11;
    atomicAdd(&sHist[fkey(c00) >> 21], 1u);
    atomicAdd(&sHist[fkey(c01) >> 21], 1u);
    atomicAdd(&sHist[fkey(c10) >> 21], 1u);
    atomicAdd(&sHist[fkey(c11) >> 21], 1u);
    __syncthreads();
    for (int e = t; e < 2048; e += 256) {
        unsigned v = sHist[e];
        if (v) atomicAdd(&g_hist[e], v);
    }
}

// ---------------- k_sel1: find bin holding the 12th-largest -----------------
__global__ void k_sel1() {
    __shared__ unsigned sfx[257];
    __shared__ unsigned sh[2048];
    int t = threadIdx.x;                                // 256
    unsigned part = 0;
    for (int q = 0; q < 8; q++) { unsigned v = g_hist[t * 8 + q]; sh[t * 8 + q] = v; part += v; }
    sfx[t] = part;
    if (t == 0) sfx[256] = 0;
    __syncthreads();
    for (int off = 1; off < 256; off <<= 1) {
        unsigned v = (t + off < 256) ? sfx[t + off] : 0u;
        __syncthreads();
        sfx[t] += v;
        __syncthreads();
    }
    unsigned cum = (t < 255) ? sfx[t + 1] : 0u;         // count strictly above my range
    for (int b = t * 8 + 7; b >= t * 8; b--) {
        unsigned c2 = cum + sh[b];
        if (cum < TOPK && c2 >= TOPK) { g_selbin = (unsigned)b; g_selrank = TOPK - cum; }
        cum = c2;
    }
}

// ---------------- k_gather: collect candidates in selected bin --------------
__global__ void k_gather() {
    int idx = (blockIdx.x * 256 + threadIdx.x) * 4;     // 256 blocks
    unsigned b = g_selbin;
    float4 v = *(const float4*)&g_A[idx];
    float vv[4] = {v.x, v.y, v.z, v.w};
#pragma unroll
    for (int q = 0; q < 4; q++) {
        unsigned key = fkey(vv[q]);
        if ((key >> 21) == b) {
            int pos = atomicAdd(&g_nc2, 1);
            if (pos < CAND_CAP) g_cand2[pos] = key;
        }
    }
}

// ---------------- k_sel2: r-th largest within bin (1 warp) ------------------
__global__ void k_sel2() {
    int lane = threadIdx.x;
    int n = g_nc2; if (n > CAND_CAP) n = CAND_CAP;
    unsigned top[TOPK];
#pragma unroll
    for (int s = 0; s < TOPK; s++) top[s] = 0u;
    for (int i = lane; i < n; i += 32) {
        unsigned k = g_cand2[i];
        if (k > top[TOPK - 1]) {
            top[TOPK - 1] = k;
#pragma unroll
            for (int s = TOPK - 1; s > 0; s--)
                if (top[s] > top[s - 1]) { unsigned tmp = top[s]; top[s] = top[s - 1]; top[s - 1] = tmp; }
        }
    }
    int r = (int)g_selrank;
    unsigned kth = 0;
    for (int it = 0; it < r; it++) {
        unsigned gm = __reduce_max_sync(0xffffffffu, top[0]);
        kth = gm;
        unsigned bal = __ballot_sync(0xffffffffu, top[0] == gm);
        if (lane == (__ffs(bal) - 1)) {
#pragma unroll
            for (int s = 0; s < TOPK - 1; s++) top[s] = top[s + 1];
            top[TOPK - 1] = 0u;
        }
    }
    if (lane == 0) g_kthkey = kth;
}

// ---------------- k_adj: write adj output + compact edges -------------------
__global__ void k_adj(float* adj_out) {
    int idx = blockIdx.x * 256 + threadIdx.x;
    if (idx >= NN * NN) return;
    float v = g_A[idx];
    float o = (fkey(v) > g_kthkey) ? 1.f : 0.f;
    if (adj_out) adj_out[idx] = o;
    if (o != 0.f) {
        int s = atomicAdd(&g_ne_raw, 1);
        if (s < MAXE) { g_ei_raw[s] = idx >> 9; g_ej_raw[s] = idx & 511; }
    }
}

// ---------------- k_prep: sort edges, build row/col index maps --------------
__global__ void k_prep() {
    int ne = g_ne_raw; if (ne > MAXE) ne = MAXE;
    int ei[MAXE], ej[MAXE];
    for (int e = 0; e < ne; e++) { ei[e] = g_ei_raw[e]; ej[e] = g_ej_raw[e]; }
    for (int a = 1; a < ne; a++) {
        int ki = ei[a], kj = ej[a]; int key = ki * NN + kj; int b = a - 1;
        while (b >= 0 && ei[b] * NN + ej[b] > key) { ei[b+1] = ei[b]; ej[b+1] = ej[b]; b--; }
        ei[b+1] = ki; ej[b+1] = kj;
    }
    int nr = 0, ncl = 0;
    int rows[MAXR], cols[MAXR];
    int e;
    for (e = 0; e < ne; e++) {
        int r = -1; for (int q = 0; q < nr; q++) if (rows[q] == ei[e]) r = q;
        int c = -1; for (int q = 0; q < ncl; q++) if (cols[q] == ej[e]) c = q;
        if (r < 0 && nr >= MAXR) break;
        if (c < 0 && ncl >= MAXR) break;
        if (r < 0) { r = nr; rows[nr++] = ei[e]; }
        if (c < 0) { c = ncl; cols[ncl++] = ej[e]; }
        g_ei[e] = ei[e]; g_ej[e] = ej[e]; g_erow[e] = r; g_ecol[e] = c;
    }
    g_ne = e; g_nrows = nr; g_ncols = ncl;
    for (int q = 0; q < nr; q++)  g_rows[q] = rows[q];
    for (int q = 0; q < ncl; q++) g_cols[q] = cols[q];
}

// ---------------- k_head: stream W_stack once; double-buffered --------------
// per head h: w1[256], w2[256], WhN[j<ncols][64]
__global__ void __launch_bounds__(256) k_head(const float* __restrict__ X,
                                              const float* __restrict__ Wst,
                                              const float* __restrict__ ast) {
    __shared__ float sW[2][64 * 68];      // [f][k] stride 68, float4-aligned
    __shared__ float sXc[MAXR][260];
    __shared__ float sA[128];
    int h = blockIdx.x, t = threadIdx.x;
    const float4* W4 = (const float4*)(Wst + (size_t)h * FIN * HF);
    // stage tile 0 early
    float4 st[4];
#pragma unroll
    for (int q = 0; q < 4; q++) st[q] = W4[q * 256 + t];
    int ncols = g_ncols; if (ncols > MAXR) ncols = MAXR;
    if (t < 128) sA[t] = ast[h * 128 + t];
    for (int e = t; e < MAXR * 256; e += 256) {
        int c = e >> 8, f = e & 255;
        sXc[c][f] = (c < ncols) ? X[g_cols[c] * FIN + f] : 0.f;
    }
    int j = t >> 4, kq = t & 15;
    int fdot = t >> 2, qq = t & 3, kd0 = qq * 16;
    float acc[4] = {0.f, 0.f, 0.f, 0.f};
    int cur = 0;
    for (int ft = 0; ft < 4; ft++) {
        // commit staged tile to smem (padded layout)
#pragma unroll
        for (int q = 0; q < 4; q++) {
            int flat = 4 * (q * 256 + t);
            int fl = flat >> 6, k = flat & 63;
            *(float4*)&sW[cur][fl * 68 + k] = st[q];
        }
        __syncthreads();
        if (ft < 3) {
#pragma unroll
            for (int q = 0; q < 4; q++) st[q] = W4[(ft + 1) * 1024 + q * 256 + t];
        }
        // w1/w2 dot for this tile's 64 f rows
        {
            float s1 = 0.f, s2 = 0.f;
#pragma unroll
            for (int k = 0; k < 16; k++) {
                float w = sW[cur][fdot * 68 + kd0 + k];
                s1 += w * sA[kd0 + k];
                s2 += w * sA[64 + kd0 + k];
            }
            s1 += __shfl_xor_sync(~0u, s1, 1); s2 += __shfl_xor_sync(~0u, s2, 1);
            s1 += __shfl_xor_sync(~0u, s1, 2); s2 += __shfl_xor_sync(~0u, s2, 2);
            if (qq == 0) {
                g_w1[h * FIN + ft * 64 + fdot] = s1;
                g_w2[h * FIN + ft * 64 + fdot] = s2;
            }
        }
        // WhN main loop: thread = (j, k-quad)
        if (j < ncols) {
#pragma unroll 8
            for (int f = 0; f < 64; f++) {
                float x = sXc[j][ft * 64 + f];
                float4 w = *(const float4*)&sW[cur][f * 68 + kq * 4];
                acc[0] += x * w.x; acc[1] += x * w.y; acc[2] += x * w.z; acc[3] += x * w.w;
            }
        }
        __syncthreads();
        cur ^= 1;
    }
    if (j < ncols) {
        float4 o = make_float4(acc[0], acc[1], acc[2], acc[3]);
        *(float4*)&g_WhN[((size_t)h * MAXR + j) * HF + kq * 4] = o;
    }
}

// ---------------- k_e2: E2T[h][j] = sum_f w2[h][f] * X[j][f] ----------------
__global__ void __launch_bounds__(256) k_e2(const float* __restrict__ X) {
    __shared__ float sA2[32 * 33], sB2[32 * 33];
    int h0 = blockIdx.y * 32, j0 = blockIdx.x * 32;
    int t = threadIdx.x;
    int ty = t >> 4, tx = t & 15;
    float c00 = 0, c01 = 0, c10 = 0, c11 = 0;
    for (int f0 = 0; f0 < FIN; f0 += 32) {
        __syncthreads();
        for (int e = t; e < 1024; e += 256) {
            int r = e >> 5, f = e & 31;
            sA2[r * 33 + f] = g_w2[(h0 + r) * FIN + f0 + f];
            sB2[r * 33 + f] = X[(j0 + r) * FIN + f0 + f];
        }
        __syncthreads();
#pragma unroll
        for (int f = 0; f < 32; f++) {
            float a0 = sA2[(2 * ty) * 33 + f],     a1 = sA2[(2 * ty + 1) * 33 + f];
            float b0 = sB2[(2 * tx) * 33 + f],     b1 = sB2[(2 * tx + 1) * 33 + f];
            c00 += a0 * b0; c01 += a0 * b1; c10 += a1 * b0; c11 += a1 * b1;
        }
    }
    g_E2T[(h0 + 2 * ty) * NN + j0 + 2 * tx]         = c00;
    g_E2T[(h0 + 2 * ty) * NN + j0 + 2 * tx + 1]     = c01;
    g_E2T[(h0 + 2 * ty + 1) * NN + j0 + 2 * tx]     = c10;
    g_E2T[(h0 + 2 * ty + 1) * NN + j0 + 2 * tx + 1] = c11;
}

// ---------------- k_epi: per-head softmax rows + mid ------------------------
__global__ void __launch_bounds__(256) k_epi(const float* __restrict__ X) {
    __shared__ float sE2[512];
    __shared__ float sE1a[MAXR], sM[MAXR], sDi[MAXR];
    __shared__ float sOut[MAXR * 64];
    __shared__ float sRed[8];
    __shared__ float sMax;
    int h = blockIdx.x, t = threadIdx.x;
    int nrows = g_nrows; if (nrows > MAXR) nrows = MAXR;
    int ne = g_ne;
    sE2[t]       = g_E2T[h * NN + t];
    sE2[t + 256] = g_E2T[h * NN + t + 256];
    int wid = t >> 5, lane = t & 31;
    // block max of e2
    float m = fmaxf(sE2[t], sE2[t + 256]);   // own values, no sync needed yet
    for (int o = 16; o; o >>= 1) m = fmaxf(m, __shfl_xor_sync(~0u, m, o));
    if (lane == 0) sRed[wid] = m;
    // E1 rows: warp wid handles rows wid and wid+8; keep in regs
    float e1v[2] = {0.f, 0.f};
#pragma unroll
    for (int rr = 0; rr < 2; rr++) {
        int r = wid + 8 * rr;
        if (r < nrows) {
            int i = g_rows[r];
            float s = 0.f;
            for (int f = lane; f < FIN; f += 32) s += X[i * FIN + f] * g_w1[h * FIN + f];
            for (int o = 16; o; o >>= 1) s += __shfl_xor_sync(~0u, s, o);
            e1v[rr] = s;
            if (lane == 0) sE1a[r] = s;
        }
    }
    for (int e = t; e < MAXR * 64; e += 256) sOut[e] = 0.f;
    __syncthreads();
    if (t == 0) {
        float mm = sRed[0];
        for (int w = 1; w < 8; w++) mm = fmaxf(mm, sRed[w]);
        sMax = mm;
    }
    __syncthreads();
    float e2max = sMax;
    // denominators: warp per row (2 rows per warp), full 512 cols
#pragma unroll
    for (int rr = 0; rr < 2; rr++) {
        int r = wid + 8 * rr;
        if (r < nrows) {
            float e1 = e1v[rr];
            float mr = lrelu(e1 + e2max);
            float p = 0.f;
            for (int c = lane; c < NN; c += 32) p += __expf(lrelu(e1 + sE2[c]) - mr);
            for (int o = 16; o; o >>= 1) p += __shfl_xor_sync(~0u, p, o);
            if (lane == 0) { sM[r] = mr; sDi[r] = 1.f / p; }
        }
    }
    __syncthreads();
    // sparse A @ Wh over edges
    if (t < 64) {
        for (int e = 0; e < ne; e++) {
            int r = g_erow[e], ci = g_ecol[e], jj = g_ej[e];
            float alpha = __expf(lrelu(sE1a[r] + sE2[jj]) - sM[r]) * sDi[r];
            sOut[r * 64 + t] += alpha * g_WhN[((size_t)h * MAXR + ci) * HF + t];
        }
    }
    __syncthreads();
    for (int e = t; e < nrows * 64; e += 256) {
        int r = e >> 6, k = e & 63;
        g_mid[(size_t)r * (NN * HF) + h * 64 + k] = elu1(sOut[r * 64 + k]);
    }
}

// ---------------- k_midg: split-K GEMM mid_act @ W_out ----------------------
__global__ void __launch_bounds__(256) k_midg(const float* __restrict__ Wout) {
    __shared__ float sMid[MAXR * 256];
    int b = blockIdx.x, t = threadIdx.x;
    int nrows = g_nrows; if (nrows > MAXR) nrows = MAXR;
    int r0 = b * 256;
    for (int e = t; e < MAXR * 256; e += 256) {
        int i = e >> 8, rr = e & 255;
        sMid[e] = (i < nrows) ? g_mid[(size_t)i * (NN * HF) + r0 + rr] : 0.f;
    }
    __syncthreads();
    int c = t & 63, ig = t >> 6;
    float acc[4] = {0.f, 0.f, 0.f, 0.f};
    for (int rr = 0; rr < 256; rr++) {
        float w = Wout[(size_t)(r0 + rr) * NC + c];
#pragma unroll
        for (int l = 0; l < 4; l++) acc[l] += sMid[(ig + 4 * l) * 256 + rr] * w;
    }
#pragma unroll
    for (int l = 0; l < 4; l++)
        g_part[((size_t)b * MAXR + ig + 4 * l) * NC + c] = acc[l];
}

__global__ void k_midred() {
    int t = blockIdx.x * 256 + threadIdx.x;
    if (t < MAXR * NC) {
        float s = 0.f;
        for (int b = 0; b < 128; b++) s += g_part[b * (MAXR * NC) + t];
        g_WhOut[t] = s;
    }
}

// ---------------- k_final: output GAT layer + elu(V*out) --------------------
__global__ void k_final(const float* __restrict__ V, const float* __restrict__ aout,
                        float* __restrict__ outp) {
    __shared__ float sAo[128];
    __shared__ float e1o[MAXR], e2o[MAXR], sM2[MAXR], sD2[MAXR];
    int t = threadIdx.x;
    int nrows = g_nrows; if (nrows > MAXR) nrows = MAXR;
    int ne = g_ne;
    if (nrows == 0 || outp == 0) return;
    if (t < 128) sAo[t] = aout[t];
    __syncthreads();
    int wid = t >> 5, lane = t & 31;
    for (int r = wid; r < nrows; r += 8) {
        float s1 = 0.f, s2 = 0.f;
        for (int f = lane; f < NC; f += 32) {
            float w = g_WhOut[r * NC + f];
            s1 += w * sAo[f]; s2 += w * sAo[64 + f];
        }
        for (int o = 16; o; o >>= 1) {
            s1 += __shfl_xor_sync(~0u, s1, o);
            s2 += __shfl_xor_sync(~0u, s2, o);
        }
        if (lane == 0) { e1o[r] = s1; e2o[r] = s2; }
    }
    __syncthreads();
    if (t == 0) {
        float e2m = 0.f;   // inactive rows contribute e2 == 0 exactly
        for (int r = 0; r < nrows; r++) e2m = fmaxf(e2m, e2o[r]);
        for (int r = 0; r < nrows; r++) {
            float mm = lrelu(e1o[r] + e2m);
            float D = (float)(NN - nrows) * __expf(lrelu(e1o[r]) - mm);
            for (int q = 0; q < nrows; q++) D += __expf(lrelu(e1o[r] + e2o[q]) - mm);
            sM2[r] = mm; sD2[r] = 1.f / D;
        }
    }
    __syncthreads();
    for (int e = t; e < nrows * 64; e += 256) {
        int r = e >> 6, k = e & 63;
        float o2 = 0.f;
        for (int ed = 0; ed < ne; ed++) {
            if (g_erow[ed] != r) continue;
            int jj = g_ej[ed];
            int jr = -1;
            for (int q = 0; q < nrows; q++) if (g_rows[q] == jj) jr = q;
            if (jr < 0) continue;
            float alpha = __expf(lrelu(e1o[r] + e2o[jr]) - sM2[r]) * sD2[r];
            o2 += alpha * g_WhOut[jr * NC + k];
        }
        float g = elu1(o2);
        int i = g_rows[r];
        outp[i * NC + k] = elu1(V[i * NC + k] * g);
    }
}

// ---------------- host ------------------------------------------------------
extern "C" void kernel_launch(void* const* d_in, const int* in_sizes, int n_in,
                              void* d_out, int out_size) {
    const float* X    = (const float*)d_in[0];
    const float* Wst  = (const float*)d_in[1];
    const float* ast  = (const float*)d_in[2];
    const float* Wout = (const float*)d_in[3];
    const float* aout = (const float*)d_in[4];
    const float* V    = (const float*)d_in[5];
    float* outbuf = (float*)d_out;

    float* adj_dst  = nullptr;
    float* feat_dst = nullptr;
    if (out_size >= NN * NN + NN * NC) { adj_dst = outbuf; feat_dst = outbuf + NN * NN; }
    else if (out_size == NN * NN)      { adj_dst = outbuf; }
    else                               { feat_dst = outbuf; }

    k_zero  <<<128, 256>>>(feat_dst);
    k_vvt   <<<dim3(16, 16), 256>>>(V);
    k_sel1  <<<1, 256>>>();
    k_gather<<<256, 256>>>();
    k_sel2  <<<1, 32>>>();
    k_adj   <<<1024, 256>>>(adj_dst);
    k_prep  <<<1, 1>>>();
    k_head  <<<512, 256>>>(X, Wst, ast);
    k_e2    <<<dim3(16, 16), 256>>>(X);
    k_epi   <<<512, 256>>>(X);
    k_midg  <<<128, 256>>>(Wout);
    k_midred<<<4, 256>>>();
    k_final <<<1, 256>>>(V, aout, feat_dst);
}